// round 4
// baseline (speedup 1.0000x reference)
#include <cuda_runtime.h>
#include <cstring>

// SkelConv: masked conv1d, B=32, C_IN=103, C_OUT=206, T=8192, K=15, pad=7.
// Structure: each out-joint sees a CONTIGUOUS input-channel slice, so this is
// 25 small dense convs. FMA-bound => use packed fma.rn.f32x2, pairing the two
// f32 lanes across a batch pair (b, b+1): x staged in smem batch-interleaved
// (natural LDS.64), weights staged duplicated {w,w} (broadcast LDS.64).

#define C_IN_   103
#define C_OUT_  206
#define T_LEN   8192
#define KS      15
#define PADK    7
#define TILE_T  512          // per block t extent
#define RPT     16           // t outputs per thread
#define NTHREADS 256         // 8 co-slots x 32 lanes
#define XLOG    (TILE_T + KS - 1)   // 526 logical smem columns
#define XPITCH  560          // physical float2 per row (526 + swizzle pad)
#define NJT     25

typedef unsigned long long u64;

union F2U { float2 f; u64 u; };

__device__ __forceinline__ u64 ffma2(u64 a, u64 b, u64 c) {
    u64 d;
    asm("fma.rn.f32x2 %0, %1, %2, %3;" : "=l"(d) : "l"(a), "l"(b), "l"(c));
    return d;
}

// swizzled physical index for logical smem column tt (one pad float2 per 16)
__device__ __forceinline__ int sw(int tt) { return tt + (tt >> 4); }

extern "C" __global__ void __launch_bounds__(NTHREADS, 2)
skelconv_kernel(const float* __restrict__ x,
                const float* __restrict__ w,
                const float* __restrict__ bias,
                const float* __restrict__ mask,
                float* __restrict__ out)
{
    extern __shared__ u64 smem[];
    u64* xs = smem;                    // 15 rows x XPITCH float2 (as u64)
    u64* ws = smem + 15 * XPITCH;      // up to 14*15*15 = 3150 duplicated weights

    const int jt = blockIdx.y;
    const int t0 = blockIdx.x * TILE_T;
    const int b0 = blockIdx.z * 2;

    // input channel slice [lo, lo+cin), output channel slice [o0, o0+cout)
    int lo, cin, o0, cout;
    if (jt == 0)       { lo = 0;  cin = 11; }
    else if (jt == 1)  { lo = 0;  cin = 15; }
    else if (jt == 24) { lo = 95; cin = 8;  }
    else               { lo = 7 + (jt - 2) * 4; cin = 12; }
    if (jt == 0) { o0 = 0; cout = 14; }
    else         { o0 = 14 + (jt - 1) * 8; cout = 8; }

    const int tid = threadIdx.x;

    // ---- stage weights: masked + duplicated {w,w} ----
    const int nw = cout * cin * KS;
    for (int idx = tid; idx < nw; idx += NTHREADS) {
        int k   = idx % KS;
        int rem = idx / KS;
        int ci  = rem % cin;
        int co  = rem / cin;
        int g   = ((o0 + co) * C_IN_ + (lo + ci)) * KS + k;
        float wv = w[g] * mask[g];
        F2U u; u.f = make_float2(wv, wv);
        ws[idx] = u.u;
    }

    // ---- stage x tile: 2 batches interleaved, zero halo, swizzled ----
    const int tstart = t0 - PADK;
    for (int ci = 0; ci < cin; ++ci) {
        const float* g0 = x + ((size_t)b0 * C_IN_ + (lo + ci)) * T_LEN;
        const float* g1 = g0 + (size_t)C_IN_ * T_LEN;
        u64* row = xs + ci * XPITCH;
        for (int tt = tid; tt < XLOG; tt += NTHREADS) {
            int t = tstart + tt;
            float v0 = 0.f, v1 = 0.f;
            if (t >= 0 && t < T_LEN) { v0 = g0[t]; v1 = g1[t]; }
            F2U u; u.f = make_float2(v0, v1);
            row[sw(tt)] = u.u;
        }
    }
    __syncthreads();

    const int lane = tid & 31;
    const int slot = tid >> 5;
    // thread covers t = t0 + lane*16 + r (r = 0..15). Logical x col = lane*16 + r + k.
    // sw(16*lane + i) = 17*lane + i + (i>>4) for i in [0,31] -> constant offsets.

    for (int cp = 0; cp < 2; ++cp) {
        const int co = slot + cp * 8;
        if (co >= cout) break;

        const float bsv = bias[o0 + co];
        F2U bu; bu.f = make_float2(bsv, bsv);
        u64 acc[RPT];
        #pragma unroll
        for (int r = 0; r < RPT; ++r) acc[r] = bu.u;

        for (int ci = 0; ci < cin; ++ci) {
            const u64* xl = xs + ci * XPITCH + lane * 17;
            const u64* wr = ws + (co * cin + ci) * KS;

            u64 win[16];
            #pragma unroll
            for (int i = 0; i < 16; ++i) win[i] = xl[i + (i >> 4)];

            #pragma unroll
            for (int k = 0; k < KS; ++k) {
                const u64 wk = wr[k];
                #pragma unroll
                for (int r = 0; r < RPT; ++r)
                    acc[r] = ffma2(win[(r + k) & 15], wk, acc[r]);
                if (k < KS - 1) {
                    const int nx = 16 + k;            // logical offset within lane strip
                    win[k & 15] = xl[nx + (nx >> 4)]; // refill slot just vacated
                }
            }
        }

        // ---- store: unpack batch pair, vectorized 16B stores ----
        float o0v[RPT], o1v[RPT];
        #pragma unroll
        for (int r = 0; r < RPT; ++r) {
            F2U u; u.u = acc[r];
            o0v[r] = u.f.x;
            o1v[r] = u.f.y;
        }
        float* p0 = out + ((size_t)b0 * C_OUT_ + (o0 + co)) * T_LEN + t0 + lane * RPT;
        float* p1 = p0 + (size_t)C_OUT_ * T_LEN;
        float4* q0 = reinterpret_cast<float4*>(p0);
        float4* q1 = reinterpret_cast<float4*>(p1);
        #pragma unroll
        for (int r4 = 0; r4 < RPT / 4; ++r4) {
            q0[r4] = make_float4(o0v[4*r4+0], o0v[4*r4+1], o0v[4*r4+2], o0v[4*r4+3]);
            q1[r4] = make_float4(o1v[4*r4+0], o1v[4*r4+1], o1v[4*r4+2], o1v[4*r4+3]);
        }
    }
}

extern "C" void kernel_launch(void* const* d_in, const int* in_sizes, int n_in,
                              void* d_out, int out_size)
{
    const float* x    = (const float*)d_in[0];
    const float* w    = (const float*)d_in[1];
    const float* bias = (const float*)d_in[2];
    const float* mask = (const float*)d_in[3];
    float* out        = (float*)d_out;

    const int smem_bytes = (15 * XPITCH + 14 * 15 * KS) * (int)sizeof(u64); // 92400
    cudaFuncSetAttribute(skelconv_kernel,
                         cudaFuncAttributeMaxDynamicSharedMemorySize, smem_bytes);

    dim3 grid(T_LEN / TILE_T, NJT, 16);   // (16, 25, 16) — B=32 as 16 batch pairs
    skelconv_kernel<<<grid, NTHREADS, smem_bytes>>>(x, w, bias, mask, out);
}

// round 5
// speedup vs baseline: 1.2523x; 1.2523x over previous
#include <cuda_runtime.h>

// SkelConv: masked conv1d, B=32, C_IN=103, C_OUT=206, T=8192, K=15, pad=7.
// 25 dense channel-slice convs; packed fma.rn.f32x2 over a batch pair.
// R5: occupancy 2->3 blocks/SM: non-duplicated weights in smem (dup at use
// via mov.b64 {f,f}), tightened pitch, __launch_bounds__(256,3).

#define C_IN_   103
#define C_OUT_  206
#define T_LEN   8192
#define KS      15
#define PADK    7
#define TILE_T  512
#define RPT     16
#define NTHREADS 256
#define XLOG    (TILE_T + KS - 1)   // 526 logical columns
#define XPHYS   558                 // 526 + 32 swizzle pads (max sw(525)=557)
#define WMAX    2310                // max cout*cin*K = 14*11*15 (jt0)
#define NJT     25

typedef unsigned long long u64;

union F2U { float2 f; u64 u; };

__device__ __forceinline__ u64 ffma2(u64 a, u64 b, u64 c) {
    u64 d;
    asm("fma.rn.f32x2 %0, %1, %2, %3;" : "=l"(d) : "l"(a), "l"(b), "l"(c));
    return d;
}

__device__ __forceinline__ u64 dup2(float f) {
    u64 d;
    asm("mov.b64 %0, {%1, %1};" : "=l"(d) : "f"(f));
    return d;
}

// swizzle: one pad float2 per 16 logical columns
__device__ __forceinline__ int sw(int tt) { return tt + (tt >> 4); }

extern "C" __global__ void __launch_bounds__(NTHREADS, 3)
skelconv_kernel(const float* __restrict__ x,
                const float* __restrict__ w,
                const float* __restrict__ bias,
                const float* __restrict__ mask,
                float* __restrict__ out)
{
    extern __shared__ u64 smem[];
    u64*   xs = smem;                              // 15 x XPHYS float2 (u64)
    float* ws = (float*)(smem + 15 * XPHYS);       // <= WMAX floats, masked

    const int jt = blockIdx.y;
    const int t0 = blockIdx.x * TILE_T;
    const int b0 = blockIdx.z * 2;

    int lo, cin, o0, cout;
    if (jt == 0)       { lo = 0;  cin = 11; }
    else if (jt == 1)  { lo = 0;  cin = 15; }
    else if (jt == 24) { lo = 95; cin = 8;  }
    else               { lo = 7 + (jt - 2) * 4; cin = 12; }
    if (jt == 0) { o0 = 0; cout = 14; }
    else         { o0 = 14 + (jt - 1) * 8; cout = 8; }

    const int tid = threadIdx.x;

    // ---- stage weights (masked, plain float) ----
    const int nw = cout * cin * KS;
    for (int idx = tid; idx < nw; idx += NTHREADS) {
        int k   = idx % KS;
        int rem = idx / KS;
        int ci  = rem % cin;
        int co  = rem / cin;
        int g   = ((o0 + co) * C_IN_ + (lo + ci)) * KS + k;
        ws[idx] = w[g] * mask[g];
    }

    // ---- stage x tile: batch pair interleaved, zero halo, pad-swizzled ----
    const int tstart = t0 - PADK;
    for (int ci = 0; ci < cin; ++ci) {
        const float* g0 = x + ((size_t)b0 * C_IN_ + (lo + ci)) * T_LEN;
        const float* g1 = g0 + (size_t)C_IN_ * T_LEN;
        u64* row = xs + ci * XPHYS;
        for (int tt = tid; tt < XLOG; tt += NTHREADS) {
            int t = tstart + tt;
            float v0 = 0.f, v1 = 0.f;
            if (t >= 0 && t < T_LEN) { v0 = g0[t]; v1 = g1[t]; }
            F2U u; u.f = make_float2(v0, v1);
            row[sw(tt)] = u.u;
        }
    }
    __syncthreads();

    const int lane = tid & 31;
    const int slot = tid >> 5;
    // thread covers t = t0 + lane*16 + r (r=0..15); sw(lane*16+off) = lane*17 + off + (off>>4)

    for (int cp = 0; cp < 2; ++cp) {
        const int co = slot + cp * 8;
        if (co >= cout) break;

        u64 acc[RPT];
        const u64 bz = dup2(bias[o0 + co]);
        #pragma unroll
        for (int r = 0; r < RPT; ++r) acc[r] = bz;

        for (int ci = 0; ci < cin; ++ci) {
            const u64*   xl = xs + ci * XPHYS + lane * 17;
            const float* wr = ws + (co * cin + ci) * KS;

            u64 win[16];
            #pragma unroll
            for (int i = 0; i < 16; ++i) win[i] = xl[i + (i >> 4)];

            #pragma unroll
            for (int k = 0; k < KS; ++k) {
                const u64 wk = dup2(wr[k]);
                #pragma unroll
                for (int r = 0; r < RPT; ++r)
                    acc[r] = ffma2(win[(r + k) & 15], wk, acc[r]);
                if (k < KS - 1) {
                    const int nx = 16 + k;
                    win[k & 15] = xl[nx + (nx >> 4)];
                }
            }
        }

        float o0v[RPT], o1v[RPT];
        #pragma unroll
        for (int r = 0; r < RPT; ++r) {
            F2U u; u.u = acc[r];
            o0v[r] = u.f.x;
            o1v[r] = u.f.y;
        }
        float* p0 = out + ((size_t)b0 * C_OUT_ + (o0 + co)) * T_LEN + t0 + lane * RPT;
        float* p1 = p0 + (size_t)C_OUT_ * T_LEN;
        float4* q0 = reinterpret_cast<float4*>(p0);
        float4* q1 = reinterpret_cast<float4*>(p1);
        #pragma unroll
        for (int r4 = 0; r4 < RPT / 4; ++r4) {
            q0[r4] = make_float4(o0v[4*r4+0], o0v[4*r4+1], o0v[4*r4+2], o0v[4*r4+3]);
            q1[r4] = make_float4(o1v[4*r4+0], o1v[4*r4+1], o1v[4*r4+2], o1v[4*r4+3]);
        }
    }
}

extern "C" void kernel_launch(void* const* d_in, const int* in_sizes, int n_in,
                              void* d_out, int out_size)
{
    const float* x    = (const float*)d_in[0];
    const float* w    = (const float*)d_in[1];
    const float* bias = (const float*)d_in[2];
    const float* mask = (const float*)d_in[3];
    float* out        = (float*)d_out;

    const int smem_bytes = 15 * XPHYS * 8 + WMAX * 4;   // 66960 + 9240 = 76200
    cudaFuncSetAttribute(skelconv_kernel,
                         cudaFuncAttributeMaxDynamicSharedMemorySize, smem_bytes);

    dim3 grid(T_LEN / TILE_T, NJT, 16);   // (16, 25, 16), B=32 as 16 batch pairs
    skelconv_kernel<<<grid, NTHREADS, smem_bytes>>>(x, w, bias, mask, out);
}

// round 7
// speedup vs baseline: 1.2992x; 1.0375x over previous
#include <cuda_runtime.h>

// SkelConv: masked conv1d, B=32, C_IN=103, C_OUT=206, T=8192, K=15, pad=7.
// 25 dense channel-slice convs; packed fma.rn.f32x2 over a batch pair.
// R6: 2 output channels per pass sharing one x-window (halves x-LDS per FFMA2),
// group-transposed x smem layout (tt -> (tt&7)*66 + (tt>>3)) giving
// compile-time window offsets and conflict-free stride-1 LDS.64,
// packed weight pairs {w_co0, w_co1} -> one broadcast LDS.64 per k.

#define C_IN_   103
#define C_OUT_  206
#define T_LEN   8192
#define KS      15
#define PADK    7
#define TILE_T  512
#define RPT     8
#define NTHREADS 256
#define XLOG    (TILE_T + KS - 1)   // 526 logical columns
#define GRP     66                  // ceil(526/8) : entries per residue group
#define ROWU    (8 * GRP)           // 528 u64 per channel row
#define WPMAX   1155                // max pairs*cin*K = 7*11*15 (jt0)
#define NJT     25

typedef unsigned long long u64;

union F2U { float2 f; u64 u; };

__device__ __forceinline__ u64 ffma2(u64 a, u64 b, u64 c) {
    u64 d;
    asm("fma.rn.f32x2 %0, %1, %2, %3;" : "=l"(d) : "l"(a), "l"(b), "l"(c));
    return d;
}

__device__ __forceinline__ u64 dup2(float f) {
    u64 d;
    asm("mov.b64 %0, {%1, %1};" : "=l"(d) : "f"(f));
    return d;
}

// group-transposed physical index for logical column tt
__device__ __forceinline__ int gt(int tt) { return (tt & 7) * GRP + (tt >> 3); }

extern "C" __global__ void __launch_bounds__(NTHREADS, 3)
skelconv_kernel(const float* __restrict__ x,
                const float* __restrict__ w,
                const float* __restrict__ bias,
                const float* __restrict__ mask,
                float* __restrict__ out)
{
    extern __shared__ u64 smem[];
    u64* xs  = smem;                   // 15 x ROWU u64 (batch-pair float2)
    u64* ws2 = smem + 15 * ROWU;       // packed weight pairs, <= WPMAX

    const int jt = blockIdx.y;
    const int t0 = blockIdx.x * TILE_T;
    const int b0 = blockIdx.z * 2;

    int lo, cin, o0, cout;
    if (jt == 0)       { lo = 0;  cin = 11; }
    else if (jt == 1)  { lo = 0;  cin = 15; }
    else if (jt == 24) { lo = 95; cin = 8;  }
    else               { lo = 7 + (jt - 2) * 4; cin = 12; }
    if (jt == 0) { o0 = 0; cout = 14; }
    else         { o0 = 14 + (jt - 1) * 8; cout = 8; }

    const int tid = threadIdx.x;

    // ---- stage weights: masked, packed per co-pair {w_2p, w_2p+1} ----
    const int npairs = cout >> 1;                 // cout always even (14 or 8)
    const int nw = npairs * cin * KS;
    for (int idx = tid; idx < nw; idx += NTHREADS) {
        int k   = idx % KS;
        int rem = idx / KS;
        int ci  = rem % cin;
        int pp  = rem / cin;
        int g0  = ((o0 + 2 * pp) * C_IN_ + (lo + ci)) * KS + k;
        int g1  = g0 + C_IN_ * KS;
        F2U u; u.f = make_float2(w[g0] * mask[g0], w[g1] * mask[g1]);
        ws2[idx] = u.u;
    }

    // ---- stage x tile: batch pair interleaved, zero halo, group-transposed ----
    const int tstart = t0 - PADK;
    for (int ci = 0; ci < cin; ++ci) {
        const float* g0 = x + ((size_t)b0 * C_IN_ + (lo + ci)) * T_LEN;
        const float* g1 = g0 + (size_t)C_IN_ * T_LEN;
        u64* row = xs + ci * ROWU;
        for (int tt = tid; tt < XLOG; tt += NTHREADS) {
            int t = tstart + tt;
            float v0 = 0.f, v1 = 0.f;
            if (t >= 0 && t < T_LEN) { v0 = g0[t]; v1 = g1[t]; }
            F2U u; u.f = make_float2(v0, v1);
            row[gt(tt)] = u.u;
        }
    }
    __syncthreads();

    const int lane = tid & 31;
    const int warp = tid >> 5;

    // task = (co-pair p, t-half h); ntasks = cout (14 for jt0, else 8)
    for (int task = warp; task < cout; task += 8) {
        const int p = task >> 1;
        const int h = task & 1;
        const int xoff = 32 * h + lane;   // base group-index for this thread

        u64 acc0[RPT], acc1[RPT];
        const u64 b0z = dup2(bias[o0 + 2 * p]);
        const u64 b1z = dup2(bias[o0 + 2 * p + 1]);
        #pragma unroll
        for (int r = 0; r < RPT; ++r) { acc0[r] = b0z; acc1[r] = b1z; }

        for (int ci = 0; ci < cin; ++ci) {
            const u64* xb = xs + ci * ROWU + xoff;
            const u64* wp = ws2 + (p * cin + ci) * KS;

            u64 win[8];
            #pragma unroll
            for (int j = 0; j < 8; ++j) win[j] = xb[j * GRP];   // gt(j), j<8

            #pragma unroll
            for (int k = 0; k < KS; ++k) {
                F2U wu; wu.u = wp[k];
                const u64 w0 = dup2(wu.f.x);
                const u64 w1 = dup2(wu.f.y);
                #pragma unroll
                for (int r = 0; r < RPT; ++r) {
                    const u64 xv = win[(r + k) & 7];
                    acc0[r] = ffma2(xv, w0, acc0[r]);
                    acc1[r] = ffma2(xv, w1, acc1[r]);
                }
                if (k < KS - 1) {
                    const int c = 8 + k;                        // next logical col
                    win[k & 7] = xb[(c & 7) * GRP + (c >> 3)];  // const offsets
                }
            }
        }

        // ---- store: unpack batch pair, 16B vector stores ----
        float a0[RPT], a1[RPT], c0[RPT], c1[RPT];
        #pragma unroll
        for (int r = 0; r < RPT; ++r) {
            F2U u; u.u = acc0[r]; a0[r] = u.f.x; a1[r] = u.f.y;
            F2U v; v.u = acc1[r]; c0[r] = v.f.x; c1[r] = v.f.y;
        }
        const int tbase = t0 + 256 * h + lane * RPT;
        float* p00 = out + ((size_t)b0 * C_OUT_ + (o0 + 2 * p)) * T_LEN + tbase;
        float* p01 = p00 + (size_t)C_OUT_ * T_LEN;          // batch b0+1, co 2p
        float* p10 = p00 + T_LEN;                           // batch b0,   co 2p+1
        float* p11 = p01 + T_LEN;                           // batch b0+1, co 2p+1
        #pragma unroll
        for (int q = 0; q < RPT / 4; ++q) {
            ((float4*)p00)[q] = make_float4(a0[4*q], a0[4*q+1], a0[4*q+2], a0[4*q+3]);
            ((float4*)p01)[q] = make_float4(a1[4*q], a1[4*q+1], a1[4*q+2], a1[4*q+3]);
            ((float4*)p10)[q] = make_float4(c0[4*q], c0[4*q+1], c0[4*q+2], c0[4*q+3]);
            ((float4*)p11)[q] = make_float4(c1[4*q], c1[4*q+1], c1[4*q+2], c1[4*q+3]);
        }
    }
}

extern "C" void kernel_launch(void* const* d_in, const int* in_sizes, int n_in,
                              void* d_out, int out_size)
{
    const float* x    = (const float*)d_in[0];
    const float* w    = (const float*)d_in[1];
    const float* bias = (const float*)d_in[2];
    const float* mask = (const float*)d_in[3];
    float* out        = (float*)d_out;

    const int smem_bytes = (15 * ROWU + WPMAX) * 8;   // 63360 + 9240 = 72600
    cudaFuncSetAttribute(skelconv_kernel,
                         cudaFuncAttributeMaxDynamicSharedMemorySize, smem_bytes);

    dim3 grid(T_LEN / TILE_T, NJT, 16);   // (16, 25, 16), B=32 as 16 batch pairs
    skelconv_kernel<<<grid, NTHREADS, smem_bytes>>>(x, w, bias, mask, out);
}